// round 7
// baseline (speedup 1.0000x reference)
#include <cuda_runtime.h>
#include <cuda_bf16.h>
#include <stdint.h>
#include <math.h>

#define TSTEPS 512
#define TOTAL  (TSTEPS * 64 * 1024)      // 33554432 floats per output copy
#define NBLK2  64                        // recurrence CTAs (blocks 0..63)
#define NP1    84                        // phase-1 worker CTAs (blocks 64..147)
#define PLANE_X 33554432u                // 32768*1024 halves per X plane

// ---------------- static device scratch (no allocation) ----------------
__device__ __align__(16) float          g_P[TOTAL];                 // X@Wx+b (fp32)
__device__ __align__(16) __nv_bfloat16  g_Xb[2u * PLANE_X];         // [plane][row 32768][k 1024]
__device__ __align__(16) __nv_bfloat16  g_Wxb[2u * 1024 * 1024];    // [plane][n][k] = Wx[k][n]
__device__ __align__(16) __nv_bfloat16  g_Whb[2u * 1024 * 1024];    // [plane][n][k] = Wh[k][n]
__device__ __align__(16) __nv_bfloat16  g_Sb[2][2 * 65536];         // ping-pong [plane][64 r][1024 k]
__device__ unsigned g_cnt = 0, g_phase = 0;
__device__ unsigned g_done[256];                                    // per 128-row m-tile: 8 when ready

#define SWZ(o) ((o) ^ (((o) >> 3) & 0x70))

// ---------------- helpers ----------------
__device__ __forceinline__ uint32_t smem_u32(const void* p) {
    uint32_t a;
    asm("{ .reg .u64 t; cvta.to.shared.u64 t, %1; cvt.u32.u64 %0, t; }" : "=r"(a) : "l"(p));
    return a;
}
__device__ __forceinline__ void ldsm4(uint32_t* r, uint32_t addr) {
    asm volatile("ldmatrix.sync.aligned.m8n8.x4.shared.b16 {%0,%1,%2,%3}, [%4];"
                 : "=r"(r[0]), "=r"(r[1]), "=r"(r[2]), "=r"(r[3]) : "r"(addr));
}
__device__ __forceinline__ void mma_bf16(float* c, const uint32_t* a, const uint32_t* b) {
    asm volatile(
        "mma.sync.aligned.m16n8k16.row.col.f32.bf16.bf16.f32 "
        "{%0,%1,%2,%3}, {%4,%5,%6,%7}, {%8,%9}, {%0,%1,%2,%3};"
        : "+f"(c[0]), "+f"(c[1]), "+f"(c[2]), "+f"(c[3])
        : "r"(a[0]), "r"(a[1]), "r"(a[2]), "r"(a[3]), "r"(b[0]), "r"(b[1]));
}
__device__ __forceinline__ void cp16(uint32_t dst, const void* src) {
    asm volatile("cp.async.cg.shared.global [%0], [%1], 16;" :: "r"(dst), "l"(src) : "memory");
}
__device__ __forceinline__ void cp_commit() { asm volatile("cp.async.commit_group;" ::: "memory"); }
template <int N> __device__ __forceinline__ void cp_wait() {
    asm volatile("cp.async.wait_group %0;" :: "n"(N) : "memory");
}

// ---------------- grid barrier (blocks 0..63 only, all co-resident) ----------------
__device__ __forceinline__ void grid_bar() {
    __syncthreads();
    if (threadIdx.x == 0) {
        __threadfence();
        unsigned ph = *((volatile unsigned*)&g_phase);
        unsigned old = atomicAdd(&g_cnt, 1u);
        if (old == NBLK2 - 1) {
            g_cnt = 0;
            __threadfence();
            atomicExch(&g_phase, ph + 1u);
        } else {
            while (*((volatile unsigned*)&g_phase) == ph) { }
        }
        __threadfence();
    }
    __syncthreads();
}

// ---------------- conversion kernels ----------------
__global__ void conv_w(const float* __restrict__ W, int which)
{
    __nv_bfloat16* out = which ? g_Whb : g_Wxb;
    __shared__ float sm[64][65];
    const int n0 = blockIdx.x << 6, k0 = blockIdx.y << 6;
    const int tid = threadIdx.x;
#pragma unroll
    for (int it = 0; it < 16; it++) {
        int e = it * 256 + tid;
        int kk = e >> 6, nn = e & 63;
        sm[kk][nn] = W[(size_t)(k0 + kk) * 1024 + n0 + nn];
    }
    __syncthreads();
#pragma unroll
    for (int it = 0; it < 16; it++) {
        int e = it * 256 + tid;
        int nn = e >> 6, kk = e & 63;
        float v = sm[kk][nn];
        __nv_bfloat16 hi = __float2bfloat16(v);
        __nv_bfloat16 lo = __float2bfloat16(v - __bfloat162float(hi));
        size_t o = (size_t)(n0 + nn) * 1024 + k0 + kk;
        out[o]            = hi;
        out[o + 1048576u] = lo;
    }
}

__global__ void conv_x(const float* __restrict__ X)
{
    int v = blockIdx.x * 256 + threadIdx.x;
#pragma unroll
    for (int i = 0; i < 8; i++) {
        int f4 = v + i * 1048576;
        const float4 x = ((const float4*)X)[f4];
        size_t e0 = (size_t)f4 << 2;
        float xs[4] = {x.x, x.y, x.z, x.w};
        unsigned short hs[4], ls[4];
#pragma unroll
        for (int q = 0; q < 4; q++) {
            __nv_bfloat16 hv = __float2bfloat16(xs[q]);
            __nv_bfloat16 lv = __float2bfloat16(xs[q] - __bfloat162float(hv));
            hs[q] = __bfloat16_as_ushort(hv); ls[q] = __bfloat16_as_ushort(lv);
        }
        *(ushort4*)(g_Xb + e0)           = make_ushort4(hs[0], hs[1], hs[2], hs[3]);
        *(ushort4*)(g_Xb + e0 + PLANE_X) = make_ushort4(ls[0], ls[1], ls[2], ls[3]);
    }
}

// ---------------- fused kernel ----------------
// dyn smem:
//   p2: A ring 4 x 16K @0 | Wh 64K @65536 | pP 4K @131072 | stg @135168 | red @139520
//   p1: 2 stages x 64K @0
#define SMEM_FUSED 141824

// phase-1 A/B slab issue (64-k slab kt, double buffer, stage stride 65536)
#define P1_ISSUE(kt) do {                                                              \
    _Pragma("unroll")                                                                  \
    for (int i = 0; i < 8; i++) {                                                      \
        int id = i * 256 + tid;                                                        \
        int ku = id & 7, r = (id >> 3) & 127, p = id >> 10;                            \
        uint32_t off = (uint32_t)((((kt) & 1) << 16) + (p << 14)                       \
                       + SWZ((uint32_t)(r * 128 + ku * 16)));                          \
        cp16(su + off,         g_Xb  + (size_t)p * PLANE_X                             \
             + (size_t)(m0 + r) * 1024 + (kt) * 64 + ku * 8);                          \
        cp16(su + off + 32768, g_Wxb + (size_t)p * 1048576                             \
             + (size_t)(col0 + r) * 1024 + (kt) * 64 + ku * 8);                        \
    }                                                                                  \
    cp_commit();                                                                       \
} while (0)

// phase-2 state slab issue: slab ss (64 k), ring stage (ss&3), 16 KB
#define P2_ISSUE(ss) do {                                                              \
    _Pragma("unroll")                                                                  \
    for (int i = 0; i < 4; i++) {                                                      \
        int id = i * 256 + tid;                                                        \
        int ku = id & 7, r = (id >> 3) & 63, p = id >> 9;                              \
        uint32_t off = (uint32_t)((((ss) & 3) << 14) + (((p << 2) | (r >> 4)) << 11)   \
                       + SWZ((uint32_t)((r & 15) * 128 + ku * 16)));                   \
        cp16(su + off, Sb + (size_t)p * 65536 + (size_t)r * 1024 + (ss) * 64 + ku * 8); \
    }                                                                                  \
    cp_commit();                                                                       \
} while (0)

__global__ void __launch_bounds__(256, 1)
fused_k(const float* __restrict__ bias, const float* __restrict__ state0,
        float* __restrict__ out)
{
    extern __shared__ __align__(1024) char dyn[];
    const uint32_t su = smem_u32(dyn);
    const int tid = threadIdx.x, wid = tid >> 5, lane = tid & 31;

    // ldmatrix fragment address constants (shared by both paths)
    const int laneR = lane & 7, idq = lane >> 3;
    const int rowA = laneR + ((idq & 1) << 3), k8A = (idq >> 1) << 3;
    const int nB   = laneR + ((idq >> 1) << 3), k8B = (idq & 1) << 3;
    uint32_t swzA[4], swzB[4];
#pragma unroll
    for (int kc = 0; kc < 4; kc++) {
        swzA[kc] = SWZ((uint32_t)(rowA * 128 + (kc * 16 + k8A) * 2));
        swzB[kc] = SWZ((uint32_t)(nB   * 128 + (kc * 16 + k8B) * 2));
    }

    if (blockIdx.x >= NBLK2) {
        // ================= phase-1 worker =================
        const int wk = blockIdx.x - NBLK2;
        for (int tau = wk; tau < 2048; tau += NP1) {
            const int m0   = (tau >> 3) << 7;      // 128-row tile, timestep order
            const int col0 = (tau & 7) << 7;

            float c[16][4];
#pragma unroll
            for (int q = 0; q < 16; q++)
#pragma unroll
                for (int j = 0; j < 4; j++) c[q][j] = 0.0f;

            P1_ISSUE(0);
            for (int kt = 0; kt < 16; kt++) {
                if (kt < 15) { P1_ISSUE(kt + 1); cp_wait<1>(); } else { cp_wait<0>(); }
                __syncthreads();
                const uint32_t Ab = su + ((kt & 1) << 16) + (wid << 11);
                const uint32_t Bb = su + ((kt & 1) << 16) + 32768;
#pragma unroll
                for (int kc = 0; kc < 4; kc++) {
                    uint32_t ah[4], al[4], bb[32];
                    ldsm4(ah, Ab + swzA[kc]);
                    ldsm4(al, Ab + 16384 + swzA[kc]);
#pragma unroll
                    for (int q = 0; q < 8; q++) ldsm4(&bb[q * 4], Bb + q * 2048 + swzB[kc]);
#pragma unroll
                    for (int q = 0; q < 8; q++) {
                        mma_bf16(c[2 * q],     ah, &bb[q * 4]);
                        mma_bf16(c[2 * q + 1], ah, &bb[q * 4 + 2]);
                    }
#pragma unroll
                    for (int q = 0; q < 8; q++) {
                        mma_bf16(c[2 * q],     al, &bb[q * 4]);
                        mma_bf16(c[2 * q + 1], al, &bb[q * 4 + 2]);
                    }
#pragma unroll
                    for (int q = 0; q < 8; q++) ldsm4(&bb[q * 4], Bb + 16384 + q * 2048 + swzB[kc]);
#pragma unroll
                    for (int q = 0; q < 8; q++) {
                        mma_bf16(c[2 * q],     ah, &bb[q * 4]);
                        mma_bf16(c[2 * q + 1], ah, &bb[q * 4 + 2]);
                    }
                }
                __syncthreads();
            }

            const int r0 = m0 + (wid << 4) + (lane >> 2);
#pragma unroll
            for (int nb = 0; nb < 16; nb++) {
                int colp = col0 + nb * 8 + ((lane & 3) << 1);
                float2 bb2 = *(const float2*)&bias[colp];
                *(float2*)&g_P[(size_t)r0 * 1024 + colp] =
                    make_float2(c[nb][0] + bb2.x, c[nb][1] + bb2.y);
                *(float2*)&g_P[(size_t)(r0 + 8) * 1024 + colp] =
                    make_float2(c[nb][2] + bb2.x, c[nb][3] + bb2.y);
            }
            __threadfence();
            __syncthreads();
            if (tid == 0) atomicAdd(&g_done[tau >> 3], 1u);
        }
        return;
    }

    // ================= phase-2 persistent recurrence =================
    const int rg = wid & 3;          // rowgroup: rows rg*16 .. +15
    const int ch = wid >> 2;         // column half: cols ch*8 .. +7 (of 16)
    const int n0 = blockIdx.x << 4;  // CTA owns 16 columns

    // resident Wh slice @65536: [p][slab16][n16][128B] swizzled (64 KB)
#pragma unroll 4
    for (int i = 0; i < 16; i++) {
        int id = i * 256 + tid;                  // 4096 uint4
        int ku = id & 127, n = (id >> 7) & 15, p = id >> 11;
        uint4 v = *(const uint4*)(g_Whb + (size_t)p * 1048576 + (size_t)(n0 + n) * 1024 + ku * 8);
        uint32_t off = 65536u + (uint32_t)((((p << 4) + (ku >> 3)) << 11)
                       + SWZ((uint32_t)(n * 128 + (ku & 7) * 16)));
        *(uint4*)(dyn + off) = v;
    }
    // init ping state from state0 (1 float4 per thread, 64*256 = 16384 total)
    {
        int f4 = blockIdx.x * 256 + tid;
        float4 x = ((const float4*)state0)[f4];
        size_t e0 = (size_t)f4 << 2;
        float xs[4] = {x.x, x.y, x.z, x.w};
        unsigned short hs[4], ls[4];
#pragma unroll
        for (int q = 0; q < 4; q++) {
            __nv_bfloat16 hv = __float2bfloat16(xs[q]);
            __nv_bfloat16 lv = __float2bfloat16(xs[q] - __bfloat162float(hv));
            hs[q] = __bfloat16_as_ushort(hv); ls[q] = __bfloat16_as_ushort(lv);
        }
        *(ushort4*)(&g_Sb[0][e0])         = make_ushort4(hs[0], hs[1], hs[2], hs[3]);
        *(ushort4*)(&g_Sb[0][e0 + 65536]) = make_ushort4(ls[0], ls[1], ls[2], ls[3]);
    }
    __threadfence();
    grid_bar();

    float* pP   = (float*)(dyn + 131072);         // [64][16] fp32
    float* stg  = (float*)(dyn + 135168);         // [64][17]
    float* psum = (float*)(dyn + 139520);         // [16][16]
    float* psq  = psum + 256;
    float* cmu  = psq + 256;                      // [16]
    float* cinv = cmu + 16;                       // [16]
    const int j = tid & 15, hg = tid >> 4;        // epilogue: 4 rows per thread

    for (int t = 0; t < TSTEPS; t++) {
        const __nv_bfloat16* Sb = g_Sb[t & 1];

        // wait for phase-1 tile of this timestep (usually already done)
        if (tid == 0) {
            while (*((volatile unsigned*)&g_done[t >> 1]) < 8u) { }
        }
        __syncthreads();

        // prefetch P[t] slice (own group, first committed)
        cp16(su + 131072 + tid * 16,
             g_P + (size_t)t * 65536 + (size_t)(tid >> 2) * 1024 + n0 + ((tid & 3) << 2));
        cp_commit();
        P2_ISSUE(0); P2_ISSUE(1); P2_ISSUE(2);

        float c0[4] = {0.0f, 0.0f, 0.0f, 0.0f};
        for (int s = 0; s < 16; s++) {
            if (s < 14) cp_wait<2>(); else if (s == 14) cp_wait<1>(); else cp_wait<0>();
            __syncthreads();
            const uint32_t Ab = su + ((s & 3) << 14) + (rg << 11);
            const uint32_t Bb = su + 65536 + (s << 11);
#pragma unroll
            for (int kc = 0; kc < 4; kc++) {
                uint32_t ah[4], al[4], bh[4], bl[4];
                ldsm4(ah, Ab + swzA[kc]);
                ldsm4(al, Ab + 8192 + swzA[kc]);
                ldsm4(bh, Bb + swzB[kc]);
                ldsm4(bl, Bb + 32768 + swzB[kc]);
                mma_bf16(c0, ah, bh + ch * 2);
                mma_bf16(c0, al, bh + ch * 2);
                mma_bf16(c0, ah, bl + ch * 2);
            }
            if (s < 13) P2_ISSUE(s + 3);
        }

        // ---- epilogue ----
        {
            int rr = (rg << 4) + (lane >> 2), cc = (ch << 3) + ((lane & 3) << 1);
            stg[rr * 17 + cc]           = c0[0];
            stg[rr * 17 + cc + 1]       = c0[1];
            stg[(rr + 8) * 17 + cc]     = c0[2];
            stg[(rr + 8) * 17 + cc + 1] = c0[3];
        }
        __syncthreads();

        float hv[4], ps = 0.0f, pq = 0.0f;
#pragma unroll
        for (int i = 0; i < 4; i++) {
            int r = (hg << 2) + i;
            float z = stg[r * 17 + j] + pP[r * 16 + j];
            float h = tanhf(z);
            hv[i] = h; ps += h; pq += h * h;
        }
        psum[hg * 16 + j] = ps;
        psq[hg * 16 + j]  = pq;
        __syncthreads();
        if (tid < 16) {
            float s = 0.0f, q = 0.0f;
#pragma unroll
            for (int g2 = 0; g2 < 16; g2++) { s += psum[g2 * 16 + tid]; q += psq[g2 * 16 + tid]; }
            float mu  = s * (1.0f / 64.0f);
            float var = q * (1.0f / 64.0f) - mu * mu;
            cmu[tid]  = mu;
            cinv[tid] = rsqrtf(var + 1e-5f);
        }
        __syncthreads();
        {
            float mu = cmu[j], inv = cinv[j];
            __nv_bfloat16* Sn = g_Sb[(t + 1) & 1];
#pragma unroll
            for (int i = 0; i < 4; i++) {
                int r = (hg << 2) + i;
                float sv = (hv[i] - mu) * inv;
                size_t o = ((size_t)t * 64 + r) * 1024 + n0 + j;
                out[o]                 = sv;
                out[o + (size_t)TOTAL] = sv;
                __nv_bfloat16 hb = __float2bfloat16(sv);
                __nv_bfloat16 lb = __float2bfloat16(sv - __bfloat162float(hb));
                Sn[(size_t)r * 1024 + n0 + j]         = hb;
                Sn[65536 + (size_t)r * 1024 + n0 + j] = lb;
            }
        }
        __threadfence();
        grid_bar();
    }

    // replay-safe: reset the ready flags (all p1 work was observed above)
    if (tid < 4) g_done[(blockIdx.x << 2) + tid] = 0;
}

// ---------------------------------------------------------------------------
extern "C" void kernel_launch(void* const* d_in, const int* in_sizes, int n_in,
                              void* d_out, int out_size)
{
    const float* X    = (const float*)d_in[0];   // [512,64,1024]
    const float* S0   = (const float*)d_in[1];   // [1,64,1024]
    const float* Wx   = (const float*)d_in[2];   // [1024,1024]
    const float* Wh   = (const float*)d_in[3];   // [1024,1024]
    const float* bias = (const float*)d_in[4];   // [1024]
    float* out = (float*)d_out;

    cudaFuncSetAttribute(fused_k, cudaFuncAttributeMaxDynamicSharedMemorySize, SMEM_FUSED);

    conv_w<<<dim3(16, 16), 256>>>(Wx, 0);
    conv_w<<<dim3(16, 16), 256>>>(Wh, 1);
    conv_x<<<4096, 256>>>(X);
    fused_k<<<NBLK2 + NP1, 256, SMEM_FUSED>>>(bias, S0, out);
}

// round 9
// speedup vs baseline: 1.7873x; 1.7873x over previous
#include <cuda_runtime.h>
#include <cuda_bf16.h>
#include <stdint.h>
#include <math.h>

#define TSTEPS 512
#define TOTAL  (TSTEPS * 64 * 1024)      // 33554432 floats per output copy
#define NBLK2  64                        // phase-2 persistent CTAs
#define PLANE_X 33554432u                // 32768*1024 halves per X plane

// ---------------- static device scratch (no allocation) ----------------
__device__ __align__(16) float          g_P[TOTAL];                 // X@Wx+b (fp32)
__device__ __align__(16) __nv_bfloat16  g_Xb[2u * PLANE_X];         // [plane][row 32768][k 1024]
__device__ __align__(16) __nv_bfloat16  g_Wxb[2u * 1024 * 1024];    // [plane][n][k] = Wx[k][n]
__device__ __align__(16) __nv_bfloat16  g_Whb[2u * 1024 * 1024];    // [plane][n][k] = Wh[k][n]
__device__ __align__(16) __nv_bfloat16  g_Sb[2][2 * 65536];         // ping-pong [plane][64 r][1024 k]
__device__ unsigned g_cnt = 0, g_phase = 0;

#define SWZ(o) ((o) ^ (((o) >> 3) & 0x70))

// ---------------- helpers ----------------
__device__ __forceinline__ uint32_t smem_u32(const void* p) {
    uint32_t a;
    asm("{ .reg .u64 t; cvta.to.shared.u64 t, %1; cvt.u32.u64 %0, t; }" : "=r"(a) : "l"(p));
    return a;
}
__device__ __forceinline__ void ldsm4(uint32_t* r, uint32_t addr) {
    asm volatile("ldmatrix.sync.aligned.m8n8.x4.shared.b16 {%0,%1,%2,%3}, [%4];"
                 : "=r"(r[0]), "=r"(r[1]), "=r"(r[2]), "=r"(r[3]) : "r"(addr));
}
__device__ __forceinline__ void mma_bf16(float* c, const uint32_t* a, const uint32_t* b) {
    asm volatile(
        "mma.sync.aligned.m16n8k16.row.col.f32.bf16.bf16.f32 "
        "{%0,%1,%2,%3}, {%4,%5,%6,%7}, {%8,%9}, {%0,%1,%2,%3};"
        : "+f"(c[0]), "+f"(c[1]), "+f"(c[2]), "+f"(c[3])
        : "r"(a[0]), "r"(a[1]), "r"(a[2]), "r"(a[3]), "r"(b[0]), "r"(b[1]));
}
__device__ __forceinline__ void cp16(uint32_t dst, const void* src) {
    asm volatile("cp.async.cg.shared.global [%0], [%1], 16;" :: "r"(dst), "l"(src) : "memory");
}
__device__ __forceinline__ void cp_commit() { asm volatile("cp.async.commit_group;" ::: "memory"); }
template <int N> __device__ __forceinline__ void cp_wait() {
    asm volatile("cp.async.wait_group %0;" :: "n"(N) : "memory");
}

// ---------------- split grid barrier (64 CTAs, monotonic phase) ----------------
__device__ __forceinline__ void bar_arrive() {
    __syncthreads();
    if (threadIdx.x == 0) {
        __threadfence();
        unsigned old = atomicAdd(&g_cnt, 1u);
        if (old == NBLK2 - 1) {
            g_cnt = 0;
            __threadfence();
            atomicAdd(&g_phase, 1u);
        }
    }
}
__device__ __forceinline__ void bar_wait(unsigned target) {
    if (threadIdx.x == 0) {
        while ((int)(*((volatile unsigned*)&g_phase) - target) < 0) { }
    }
    __syncthreads();
}

// ---------------- conversion kernels ----------------
__global__ void conv_w(const float* __restrict__ W, int which)
{
    __nv_bfloat16* out = which ? g_Whb : g_Wxb;
    __shared__ float sm[64][65];
    const int n0 = blockIdx.x << 6, k0 = blockIdx.y << 6;
    const int tid = threadIdx.x;
#pragma unroll
    for (int it = 0; it < 16; it++) {
        int e = it * 256 + tid;
        int kk = e >> 6, nn = e & 63;
        sm[kk][nn] = W[(size_t)(k0 + kk) * 1024 + n0 + nn];
    }
    __syncthreads();
#pragma unroll
    for (int it = 0; it < 16; it++) {
        int e = it * 256 + tid;
        int nn = e >> 6, kk = e & 63;
        float v = sm[kk][nn];
        __nv_bfloat16 hi = __float2bfloat16(v);
        __nv_bfloat16 lo = __float2bfloat16(v - __bfloat162float(hi));
        size_t o = (size_t)(n0 + nn) * 1024 + k0 + kk;
        out[o]            = hi;
        out[o + 1048576u] = lo;
    }
}

__global__ void conv_x(const float* __restrict__ X)
{
    int v = blockIdx.x * 256 + threadIdx.x;
#pragma unroll
    for (int i = 0; i < 8; i++) {
        int f4 = v + i * 1048576;
        const float4 x = ((const float4*)X)[f4];
        size_t e0 = (size_t)f4 << 2;
        float xs[4] = {x.x, x.y, x.z, x.w};
        unsigned short hs[4], ls[4];
#pragma unroll
        for (int q = 0; q < 4; q++) {
            __nv_bfloat16 hv = __float2bfloat16(xs[q]);
            __nv_bfloat16 lv = __float2bfloat16(xs[q] - __bfloat162float(hv));
            hs[q] = __bfloat16_as_ushort(hv); ls[q] = __bfloat16_as_ushort(lv);
        }
        *(ushort4*)(g_Xb + e0)           = make_ushort4(hs[0], hs[1], hs[2], hs[3]);
        *(ushort4*)(g_Xb + e0 + PLANE_X) = make_ushort4(ls[0], ls[1], ls[2], ls[3]);
    }
}

// ---------------- phase 1: P = X@Wx + b (unchanged — measured 482us, tensor 70%) ----------------
#define P1_SMEM 131072

#define P1_ISSUE(kt) do {                                                              \
    _Pragma("unroll")                                                                  \
    for (int i = 0; i < 8; i++) {                                                      \
        int id = i * 256 + tid;                                                        \
        int ku = id & 7, r = (id >> 3) & 127, p = id >> 10;                            \
        uint32_t off = (uint32_t)((((kt) & 1) << 16) + (p << 14)                       \
                       + SWZ((uint32_t)(r * 128 + ku * 16)));                          \
        cp16(su + off,         g_Xb  + (size_t)p * PLANE_X                             \
             + (size_t)(m0 + r) * 1024 + (kt) * 64 + ku * 8);                          \
        cp16(su + off + 32768, g_Wxb + (size_t)p * 1048576                             \
             + (size_t)(col0 + r) * 1024 + (kt) * 64 + ku * 8);                        \
    }                                                                                  \
    cp_commit();                                                                       \
} while (0)

__global__ void __launch_bounds__(256, 1)
gemm_p1(const float* __restrict__ bias)
{
    extern __shared__ __align__(1024) char dyn[];
    const uint32_t su = smem_u32(dyn);
    const int tid = threadIdx.x, wid = tid >> 5, lane = tid & 31;
    const int col0 = blockIdx.x << 7, m0 = blockIdx.y << 7;

    const int laneR = lane & 7, idq = lane >> 3;
    const int rowA = laneR + ((idq & 1) << 3), k8A = (idq >> 1) << 3;
    const int nB   = laneR + ((idq >> 1) << 3), k8B = (idq & 1) << 3;
    uint32_t swzA[4], swzB[4];
#pragma unroll
    for (int kc = 0; kc < 4; kc++) {
        swzA[kc] = SWZ((uint32_t)(rowA * 128 + (kc * 16 + k8A) * 2));
        swzB[kc] = SWZ((uint32_t)(nB   * 128 + (kc * 16 + k8B) * 2));
    }

    float c[16][4];
#pragma unroll
    for (int q = 0; q < 16; q++)
#pragma unroll
        for (int j = 0; j < 4; j++) c[q][j] = 0.0f;

    P1_ISSUE(0);
    for (int kt = 0; kt < 16; kt++) {
        if (kt < 15) { P1_ISSUE(kt + 1); cp_wait<1>(); } else { cp_wait<0>(); }
        __syncthreads();
        const uint32_t Ab = su + ((kt & 1) << 16) + (wid << 11);
        const uint32_t Bb = su + ((kt & 1) << 16) + 32768;
#pragma unroll
        for (int kc = 0; kc < 4; kc++) {
            uint32_t ah[4], al[4], bb[32];
            ldsm4(ah, Ab + swzA[kc]);
            ldsm4(al, Ab + 16384 + swzA[kc]);
#pragma unroll
            for (int q = 0; q < 8; q++) ldsm4(&bb[q * 4], Bb + q * 2048 + swzB[kc]);
#pragma unroll
            for (int q = 0; q < 8; q++) {
                mma_bf16(c[2 * q],     ah, &bb[q * 4]);
                mma_bf16(c[2 * q + 1], ah, &bb[q * 4 + 2]);
            }
#pragma unroll
            for (int q = 0; q < 8; q++) {
                mma_bf16(c[2 * q],     al, &bb[q * 4]);
                mma_bf16(c[2 * q + 1], al, &bb[q * 4 + 2]);
            }
#pragma unroll
            for (int q = 0; q < 8; q++) ldsm4(&bb[q * 4], Bb + 16384 + q * 2048 + swzB[kc]);
#pragma unroll
            for (int q = 0; q < 8; q++) {
                mma_bf16(c[2 * q],     ah, &bb[q * 4]);
                mma_bf16(c[2 * q + 1], ah, &bb[q * 4 + 2]);
            }
        }
        __syncthreads();
    }

    const int r0 = m0 + (wid << 4) + (lane >> 2);
#pragma unroll
    for (int nb = 0; nb < 16; nb++) {
        int colp = col0 + nb * 8 + ((lane & 3) << 1);
        float2 bb = *(const float2*)&bias[colp];
        *(float2*)&g_P[(size_t)r0 * 1024 + colp]       = make_float2(c[nb][0] + bb.x, c[nb][1] + bb.y);
        *(float2*)&g_P[(size_t)(r0 + 8) * 1024 + colp] = make_float2(c[nb][2] + bb.x, c[nb][3] + bb.y);
    }
}

// ---------------- phase 2: persistent recurrence ----------------
// 64 CTAs x 256 thr (8 warps). warp: rg = wid&3 (16 rows of 64+64 hi/lo), ch = wid>>2 (8 cols).
// Full 3-term on BOTH column halves (round-8 bug: ch==1 dropped the ah*bl term).
// smem: A ring 4 x 32K @0 | Wh 64K @131072 | pP 4K @196608 | stg @200704 | red @205056
#define P2_SMEM 207232

#define P2_ISSUE(ss) do {                                                              \
    _Pragma("unroll")                                                                  \
    for (int i = 0; i < 8; i++) {                                                      \
        int id = i * 256 + tid;                                                        \
        int ku = id & 15, r = (id >> 4) & 63, p = id >> 10;                            \
        uint32_t off = (uint32_t)((((ss) & 3) << 15)                                   \
                       + ((((p << 2) | (r >> 4)) * 2 + (ku >> 3)) << 11)               \
                       + SWZ((uint32_t)((r & 15) * 128 + (ku & 7) * 16)));             \
        cp16(su + off, Sb + (size_t)p * 65536 + (size_t)r * 1024 + (ss) * 128 + ku * 8); \
    }                                                                                  \
    cp_commit();                                                                       \
} while (0)

__global__ void __launch_bounds__(256, 1)
rnn_p2(const float* __restrict__ state0, float* __restrict__ out)
{
    extern __shared__ __align__(1024) char dyn[];
    const uint32_t su = smem_u32(dyn);
    const int tid = threadIdx.x, wid = tid >> 5, lane = tid & 31;
    const int rg = wid & 3;              // rowgroup (16 rows)
    const int ch = wid >> 2;             // column half (8 of 16 cols)
    const int n0 = blockIdx.x << 4;      // CTA owns 16 columns

    const unsigned base = *((volatile unsigned*)&g_phase);

    const int laneR = lane & 7, idq = lane >> 3;
    const int rowA = laneR + ((idq & 1) << 3), k8A = (idq >> 1) << 3;
    const int nB   = laneR + ((idq >> 1) << 3), k8B = (idq & 1) << 3;
    uint32_t swzA[4], swzB[4];
#pragma unroll
    for (int kc = 0; kc < 4; kc++) {
        swzA[kc] = SWZ((uint32_t)(rowA * 128 + (kc * 16 + k8A) * 2));
        swzB[kc] = SWZ((uint32_t)(nB   * 128 + (kc * 16 + k8B) * 2));
    }

    // resident Wh slice @131072: [p][slab16(k64)][n16][128B] swizzled (64 KB)
#pragma unroll 4
    for (int i = 0; i < 16; i++) {
        int id = i * 256 + tid;                  // 4096 uint4
        int ku = id & 127, n = (id >> 7) & 15, p = id >> 11;
        uint4 v = *(const uint4*)(g_Whb + (size_t)p * 1048576 + (size_t)(n0 + n) * 1024 + ku * 8);
        uint32_t off = 131072u + (uint32_t)((((p << 4) + (ku >> 3)) << 11)
                       + SWZ((uint32_t)(n * 128 + (ku & 7) * 16)));
        *(uint4*)(dyn + off) = v;
    }
    // init ping state from state0 (1 float4/thread, 64 CTAs x 256 = 16384)
    {
        int f4 = blockIdx.x * 256 + tid;
        float4 x = ((const float4*)state0)[f4];
        size_t e0 = (size_t)f4 << 2;
        float xs[4] = {x.x, x.y, x.z, x.w};
        unsigned short hs[4], ls[4];
#pragma unroll
        for (int q = 0; q < 4; q++) {
            __nv_bfloat16 hv = __float2bfloat16(xs[q]);
            __nv_bfloat16 lv = __float2bfloat16(xs[q] - __bfloat162float(hv));
            hs[q] = __bfloat16_as_ushort(hv); ls[q] = __bfloat16_as_ushort(lv);
        }
        *(ushort4*)(&g_Sb[0][e0])         = make_ushort4(hs[0], hs[1], hs[2], hs[3]);
        *(ushort4*)(&g_Sb[0][e0 + 65536]) = make_ushort4(ls[0], ls[1], ls[2], ls[3]);
    }
    bar_arrive();
    unsigned tgt = base + 1;

    float* pP   = (float*)(dyn + 196608);         // [64][16]
    float* stg  = (float*)(dyn + 200704);         // [64][17]
    float* psum = (float*)(dyn + 205056);         // [16][16]
    float* psq  = (float*)(dyn + 206080);         // [16][16]
    float* cmu  = (float*)(dyn + 207104);         // [16]
    float* cinv = (float*)(dyn + 207168);         // [16]
    const int j = tid & 15, hg = tid >> 4;

    for (int t = 0; t < TSTEPS; t++) {
        bar_wait(tgt);
        const __nv_bfloat16* Sb = g_Sb[t & 1];

        // P[t] prefetch: own group, committed first (retired by u=0 wait)
        cp16(su + 196608 + tid * 16,
             g_P + (size_t)t * 65536 + (size_t)(tid >> 2) * 1024 + n0 + ((tid & 3) << 2));
        cp_commit();
        P2_ISSUE(0); P2_ISSUE(1); P2_ISSUE(2);

        float c0[4] = {0.0f, 0.0f, 0.0f, 0.0f};
        float cb[4] = {0.0f, 0.0f, 0.0f, 0.0f};
        for (int u = 0; u < 8; u++) {
            if (u < 6) cp_wait<2>(); else if (u == 6) cp_wait<1>(); else cp_wait<0>();
            __syncthreads();
            if (u < 5) P2_ISSUE(u + 3);            // writes stage (u-1)&3 — safe post-sync
            const uint32_t Ab  = su + ((u & 3) << 15) + ((rg * 2) << 11);
            const uint32_t Bb0 = su + 131072 + ((u * 2) << 11);
#pragma unroll
            for (int kc = 0; kc < 8; kc++) {
                uint32_t ah[4], al[4], bh[4], bl4[4];
                uint32_t Aq = Ab + ((kc >> 2) << 11) + swzA[kc & 3];
                uint32_t Bq = Bb0 + ((kc >> 2) << 11) + swzB[kc & 3];
                ldsm4(ah, Aq);
                ldsm4(al, Aq + 16384);             // A lo plane: (4*2)<<11
                ldsm4(bh, Bq);
                ldsm4(bl4, Bq + 32768);            // Wh lo plane
                if (ch == 0) {
                    mma_bf16(c0, ah, bh);
                    mma_bf16(cb, al, bh);
                    mma_bf16(c0, ah, bl4);
                } else {
                    mma_bf16(c0, ah, bh + 2);
                    mma_bf16(cb, al, bh + 2);
                    mma_bf16(c0, ah, bl4 + 2);
                }
            }
        }

        // ---- epilogue ----
        {
            int rr = (rg << 4) + (lane >> 2), cc = (ch << 3) + ((lane & 3) << 1);
            stg[rr * 17 + cc]           = c0[0] + cb[0];
            stg[rr * 17 + cc + 1]       = c0[1] + cb[1];
            stg[(rr + 8) * 17 + cc]     = c0[2] + cb[2];
            stg[(rr + 8) * 17 + cc + 1] = c0[3] + cb[3];
        }
        __syncthreads();

        float hv[4], ps = 0.0f, pq = 0.0f;
#pragma unroll
        for (int i = 0; i < 4; i++) {
            int r = (hg << 2) + i;
            float z = stg[r * 17 + j] + pP[r * 16 + j];
            float h = tanhf(z);
            hv[i] = h; ps += h; pq += h * h;
        }
        psum[hg * 16 + j] = ps;
        psq[hg * 16 + j]  = pq;
        __syncthreads();
        if (tid < 16) {
            float s = 0.0f, q = 0.0f;
#pragma unroll
            for (int g2 = 0; g2 < 16; g2++) { s += psum[g2 * 16 + tid]; q += psq[g2 * 16 + tid]; }
            float mu  = s * (1.0f / 64.0f);
            float var = q * (1.0f / 64.0f) - mu * mu;
            cmu[tid]  = mu;
            cinv[tid] = rsqrtf(var + 1e-5f);
        }
        __syncthreads();

        float mu = cmu[j], inv = cinv[j];
        float sv[4];
        {
            __nv_bfloat16* Sn = g_Sb[(t + 1) & 1];
#pragma unroll
            for (int i = 0; i < 4; i++) {
                int r = (hg << 2) + i;
                sv[i] = (hv[i] - mu) * inv;
                __nv_bfloat16 hb = __float2bfloat16(sv[i]);
                __nv_bfloat16 lb = __float2bfloat16(sv[i] - __bfloat162float(hb));
                Sn[(size_t)r * 1024 + n0 + j]         = hb;
                Sn[65536 + (size_t)r * 1024 + n0 + j] = lb;
            }
        }
        bar_arrive();                              // release state; out stores in its shadow
        tgt++;
#pragma unroll
        for (int i = 0; i < 4; i++) {
            int r = (hg << 2) + i;
            size_t o = ((size_t)t * 64 + r) * 1024 + n0 + j;
            out[o]                 = sv[i];
            out[o + (size_t)TOTAL] = sv[i];
        }
    }
}

// ---------------------------------------------------------------------------
extern "C" void kernel_launch(void* const* d_in, const int* in_sizes, int n_in,
                              void* d_out, int out_size)
{
    const float* X    = (const float*)d_in[0];   // [512,64,1024]
    const float* S0   = (const float*)d_in[1];   // [1,64,1024]
    const float* Wx   = (const float*)d_in[2];   // [1024,1024]
    const float* Wh   = (const float*)d_in[3];   // [1024,1024]
    const float* bias = (const float*)d_in[4];   // [1024]
    float* out = (float*)d_out;

    cudaFuncSetAttribute(gemm_p1, cudaFuncAttributeMaxDynamicSharedMemorySize, P1_SMEM);
    cudaFuncSetAttribute(rnn_p2,  cudaFuncAttributeMaxDynamicSharedMemorySize, P2_SMEM);

    conv_w<<<dim3(16, 16), 256>>>(Wx, 0);
    conv_w<<<dim3(16, 16), 256>>>(Wh, 1);
    conv_x<<<4096, 256>>>(X);
    gemm_p1<<<dim3(8, 256), 256, P1_SMEM>>>(bias);
    rnn_p2<<<NBLK2, 256, P2_SMEM>>>(S0, out);
}